// round 1
// baseline (speedup 1.0000x reference)
#include <cuda_runtime.h>
#include <math.h>

#define B_ROWS   524288
#define HIST     50
#define NUMD     32
#define NCAT     8
#define CATD     16
#define REGD     32
#define INDIM    242          // 50 + 32 + 8*16 + 32
#define HID      64
#define KEXP     64
#define TOPK     8
#define HASHB    32768
#define GEOB     4096

#define NWARP    16
#define THREADS  (NWARP * 32)
#define RPW      4                       // rows per warp
#define ROWS_PER_TILE (NWARP * RPW)      // 64
#define KPAD     248                     // pad 242 -> 248 (16B-friendly)

struct Smem {
    float W1[INDIM * HID];               // 61952 B
    float W2[HID * HID];                 // 16384 B
    float W3[HID * KEXP];                // 16384 B
    float b1[HID];
    float b2[HID];
    float b3[KEXP];
    float pad[16];                        // keep xT 16B aligned
    float xT[NWARP][KPAD][RPW];          // 63488 B : x transposed [k][row]
    float hT[NWARP][HID][RPW];           // 16384 B : hidden transposed
};

__device__ __forceinline__ float warp_max(float v) {
    #pragma unroll
    for (int o = 16; o; o >>= 1) v = fmaxf(v, __shfl_xor_sync(0xffffffffu, v, o));
    return v;
}
__device__ __forceinline__ int warp_min_i(int v) {
    #pragma unroll
    for (int o = 16; o; o >>= 1) v = min(v, __shfl_xor_sync(0xffffffffu, v, o));
    return v;
}
__device__ __forceinline__ float warp_sum(float v) {
    #pragma unroll
    for (int o = 16; o; o >>= 1) v += __shfl_xor_sync(0xffffffffu, v, o);
    return v;
}
__device__ __forceinline__ float gelu_exact(float x) {
    return 0.5f * x * (1.0f + erff(x * 0.70710678118654752440f));
}

__global__ __launch_bounds__(THREADS)
void gating_kernel(const float* __restrict__ hist,
                   const float* __restrict__ num,
                   const int*   __restrict__ cat,
                   const int*   __restrict__ region,
                   const float* __restrict__ catT,
                   const float* __restrict__ regT,
                   const float* __restrict__ W1, const float* __restrict__ b1,
                   const float* __restrict__ W2, const float* __restrict__ b2,
                   const float* __restrict__ W3, const float* __restrict__ b3,
                   float* __restrict__ out)
{
    extern __shared__ float smem_raw[];
    Smem* s = reinterpret_cast<Smem*>(smem_raw);
    const int tid = threadIdx.x;

    // Stage all weights/biases once per CTA.
    for (int i = tid; i < INDIM * HID; i += THREADS) s->W1[i] = W1[i];
    for (int i = tid; i < HID * HID;   i += THREADS) s->W2[i] = W2[i];
    for (int i = tid; i < HID * KEXP;  i += THREADS) s->W3[i] = W3[i];
    if (tid < HID)  { s->b1[tid] = b1[tid]; s->b2[tid] = b2[tid]; }
    if (tid < KEXP) { s->b3[tid] = b3[tid]; }
    __syncthreads();

    const int warp = tid >> 5;
    const int lane = tid & 31;
    const int c0 = 2 * lane, c1 = 2 * lane + 1;
    float (*xT)[RPW] = s->xT[warp];
    float (*hT)[RPW] = s->hT[warp];

    const int ntiles = B_ROWS / ROWS_PER_TILE;
    for (int tile = blockIdx.x; tile < ntiles; tile += gridDim.x) {
        const int row0 = tile * ROWS_PER_TILE + warp * RPW;

        // ---- gather x for 4 rows into transposed tile xT[k][r] ----
        #pragma unroll
        for (int r = 0; r < RPW; ++r) {
            const int row = row0 + r;
            for (int k = lane; k < HIST; k += 32)
                xT[k][r] = hist[row * HIST + k];
            xT[HIST + lane][r] = num[row * NUMD + lane];
            #pragma unroll
            for (int t = lane; t < NCAT * CATD; t += 32) {
                const int j = t >> 4, d = t & 15;
                int idx = cat[row * NCAT + j];
                idx = min(max(idx, 0), HASHB - 1);
                xT[HIST + NUMD + t][r] = catT[(j * HASHB + idx) * CATD + d];
            }
            int rid = region[row];
            rid = min(max(rid, 0), GEOB - 1);
            xT[HIST + NUMD + NCAT * CATD + lane][r] = regT[rid * REGD + lane];
        }
        __syncwarp();

        // ---- layer 1: x[4,242] @ W1[242,64]  (lane owns cols c0,c1) ----
        float aA[RPW], aB[RPW];
        #pragma unroll
        for (int r = 0; r < RPW; ++r) { aA[r] = 0.f; aB[r] = 0.f; }
        #pragma unroll 2
        for (int k = 0; k < INDIM; ++k) {
            const float4 xv = *reinterpret_cast<const float4*>(xT[k]);
            const float2 w  = *reinterpret_cast<const float2*>(&s->W1[k * HID + c0]);
            const float xq[RPW] = {xv.x, xv.y, xv.z, xv.w};
            #pragma unroll
            for (int r = 0; r < RPW; ++r) { aA[r] += xq[r] * w.x; aB[r] += xq[r] * w.y; }
        }
        {
            const float bbx = s->b1[c0], bby = s->b1[c1];
            #pragma unroll
            for (int r = 0; r < RPW; ++r) {
                hT[c0][r] = gelu_exact(aA[r] + bbx);
                hT[c1][r] = gelu_exact(aB[r] + bby);
            }
        }
        __syncwarp();

        // ---- layer 2: h[4,64] @ W2[64,64] ----
        #pragma unroll
        for (int r = 0; r < RPW; ++r) { aA[r] = 0.f; aB[r] = 0.f; }
        #pragma unroll 4
        for (int k = 0; k < HID; ++k) {
            const float4 hv = *reinterpret_cast<const float4*>(hT[k]);
            const float2 w  = *reinterpret_cast<const float2*>(&s->W2[k * HID + c0]);
            const float hq[RPW] = {hv.x, hv.y, hv.z, hv.w};
            #pragma unroll
            for (int r = 0; r < RPW; ++r) { aA[r] += hq[r] * w.x; aB[r] += hq[r] * w.y; }
        }
        __syncwarp();   // everyone done reading hT before overwrite
        {
            const float bbx = s->b2[c0], bby = s->b2[c1];
            #pragma unroll
            for (int r = 0; r < RPW; ++r) {
                hT[c0][r] = gelu_exact(aA[r] + bbx);
                hT[c1][r] = gelu_exact(aB[r] + bby);
            }
        }
        __syncwarp();

        // ---- layer 3: logits = h2[4,64] @ W3[64,64] + b3 ----
        #pragma unroll
        for (int r = 0; r < RPW; ++r) { aA[r] = 0.f; aB[r] = 0.f; }
        #pragma unroll 4
        for (int k = 0; k < HID; ++k) {
            const float4 hv = *reinterpret_cast<const float4*>(hT[k]);
            const float2 w  = *reinterpret_cast<const float2*>(&s->W3[k * KEXP + c0]);
            const float hq[RPW] = {hv.x, hv.y, hv.z, hv.w};
            #pragma unroll
            for (int r = 0; r < RPW; ++r) { aA[r] += hq[r] * w.x; aB[r] += hq[r] * w.y; }
        }
        __syncwarp();   // hT reused next tile iteration
        const float b3x = s->b3[c0], b3y = s->b3[c1];

        // ---- epilogue per row: top-8 mask + softmax ----
        #pragma unroll
        for (int r = 0; r < RPW; ++r) {
            const int row = row0 + r;
            const float v0 = aA[r] + b3x;
            const float v1 = aB[r] + b3y;
            float w0 = v0, w1 = v1;
            bool  s0 = false, s1 = false;
            float vmax = 0.f;
            #pragma unroll
            for (int it = 0; it < TOPK; ++it) {
                const float m = warp_max(fmaxf(w0, w1));
                if (it == 0) vmax = m;
                int cand = KEXP;                 // smallest-column tie-break (jax top_k order)
                if (w1 == m) cand = c1;
                if (w0 == m) cand = c0;
                const int cmin = warp_min_i(cand);
                if (cand == cmin && cand < KEXP) {
                    if (cand == c0) { s0 = true; w0 = -INFINITY; }
                    else            { s1 = true; w1 = -INFINITY; }
                }
            }
            const float e0 = s0 ? expf(v0 - vmax) : 0.f;
            const float e1 = s1 ? expf(v1 - vmax) : 0.f;
            const float inv = 1.0f / warp_sum(e0 + e1);
            reinterpret_cast<float2*>(out)[row * 32 + lane] = make_float2(e0 * inv, e1 * inv);
        }
    }
}

extern "C" void kernel_launch(void* const* d_in, const int* in_sizes, int n_in,
                              void* d_out, int out_size)
{
    const float* hist   = (const float*)d_in[0];
    const float* num    = (const float*)d_in[1];
    const int*   cat    = (const int*)  d_in[2];
    const int*   region = (const int*)  d_in[3];
    const float* catT   = (const float*)d_in[4];
    const float* regT   = (const float*)d_in[5];
    const float* W1     = (const float*)d_in[6];
    const float* b1     = (const float*)d_in[7];
    const float* W2     = (const float*)d_in[8];
    const float* b2     = (const float*)d_in[9];
    const float* W3     = (const float*)d_in[10];
    const float* b3     = (const float*)d_in[11];
    float* out = (float*)d_out;

    cudaFuncSetAttribute(gating_kernel,
                         cudaFuncAttributeMaxDynamicSharedMemorySize,
                         (int)sizeof(Smem));
    gating_kernel<<<592, THREADS, sizeof(Smem)>>>(
        hist, num, cat, region, catT, regT, W1, b1, W2, b2, W3, b3, out);
}

// round 2
// speedup vs baseline: 1.0008x; 1.0008x over previous
#include <cuda_runtime.h>
#include <math.h>

#define B_ROWS   524288
#define HIST     50
#define NUMD     32
#define NCAT     8
#define CATD     16
#define REGD     32
#define INDIM    242          // 50 + 32 + 8*16 + 32
#define HID      64
#define KEXP     64
#define TOPK     8
#define HASHB    32768
#define GEOB     4096

#define NWARP    16
#define THREADS  (NWARP * 32)
#define RPW      4                       // rows per warp
#define ROWS_PER_TILE (NWARP * RPW)      // 64
#define KPAD     248                     // pad 242 -> 248 (16B-friendly)

struct Smem {
    float W1[INDIM * HID];               // 61952 B
    float W2[HID * HID];                 // 16384 B
    float W3[HID * KEXP];                // 16384 B
    float b1[HID];
    float b2[HID];
    float b3[KEXP];
    float pad[16];                        // keep xT 16B aligned
    float xT[NWARP][KPAD][RPW];          // 63488 B : x transposed [k][row]
    float hT[NWARP][HID][RPW];           // 16384 B : hidden transposed
};

__device__ __forceinline__ float warp_max(float v) {
    #pragma unroll
    for (int o = 16; o; o >>= 1) v = fmaxf(v, __shfl_xor_sync(0xffffffffu, v, o));
    return v;
}
__device__ __forceinline__ int warp_min_i(int v) {
    #pragma unroll
    for (int o = 16; o; o >>= 1) v = min(v, __shfl_xor_sync(0xffffffffu, v, o));
    return v;
}
__device__ __forceinline__ float warp_sum(float v) {
    #pragma unroll
    for (int o = 16; o; o >>= 1) v += __shfl_xor_sync(0xffffffffu, v, o);
    return v;
}
__device__ __forceinline__ float gelu_exact(float x) {
    return 0.5f * x * (1.0f + erff(x * 0.70710678118654752440f));
}

__global__ __launch_bounds__(THREADS)
void gating_kernel(const float* __restrict__ hist,
                   const float* __restrict__ num,
                   const int*   __restrict__ cat,
                   const int*   __restrict__ region,
                   const float* __restrict__ catT,
                   const float* __restrict__ regT,
                   const float* __restrict__ W1, const float* __restrict__ b1,
                   const float* __restrict__ W2, const float* __restrict__ b2,
                   const float* __restrict__ W3, const float* __restrict__ b3,
                   float* __restrict__ out)
{
    extern __shared__ float smem_raw[];
    Smem* s = reinterpret_cast<Smem*>(smem_raw);
    const int tid = threadIdx.x;

    // Stage all weights/biases once per CTA.
    for (int i = tid; i < INDIM * HID; i += THREADS) s->W1[i] = W1[i];
    for (int i = tid; i < HID * HID;   i += THREADS) s->W2[i] = W2[i];
    for (int i = tid; i < HID * KEXP;  i += THREADS) s->W3[i] = W3[i];
    if (tid < HID)  { s->b1[tid] = b1[tid]; s->b2[tid] = b2[tid]; }
    if (tid < KEXP) { s->b3[tid] = b3[tid]; }
    __syncthreads();

    const int warp = tid >> 5;
    const int lane = tid & 31;
    const int c0 = 2 * lane, c1 = 2 * lane + 1;
    float (*xT)[RPW] = s->xT[warp];
    float (*hT)[RPW] = s->hT[warp];

    const int ntiles = B_ROWS / ROWS_PER_TILE;
    for (int tile = blockIdx.x; tile < ntiles; tile += gridDim.x) {
        const int row0 = tile * ROWS_PER_TILE + warp * RPW;

        // ---- gather x for 4 rows into transposed tile xT[k][r] ----
        #pragma unroll
        for (int r = 0; r < RPW; ++r) {
            const int row = row0 + r;
            for (int k = lane; k < HIST; k += 32)
                xT[k][r] = hist[row * HIST + k];
            xT[HIST + lane][r] = num[row * NUMD + lane];
            #pragma unroll
            for (int t = lane; t < NCAT * CATD; t += 32) {
                const int j = t >> 4, d = t & 15;
                int idx = cat[row * NCAT + j];
                idx = min(max(idx, 0), HASHB - 1);
                xT[HIST + NUMD + t][r] = catT[(j * HASHB + idx) * CATD + d];
            }
            int rid = region[row];
            rid = min(max(rid, 0), GEOB - 1);
            xT[HIST + NUMD + NCAT * CATD + lane][r] = regT[rid * REGD + lane];
        }
        __syncwarp();

        // ---- layer 1: x[4,242] @ W1[242,64]  (lane owns cols c0,c1) ----
        float aA[RPW], aB[RPW];
        #pragma unroll
        for (int r = 0; r < RPW; ++r) { aA[r] = 0.f; aB[r] = 0.f; }
        #pragma unroll 2
        for (int k = 0; k < INDIM; ++k) {
            const float4 xv = *reinterpret_cast<const float4*>(xT[k]);
            const float2 w  = *reinterpret_cast<const float2*>(&s->W1[k * HID + c0]);
            const float xq[RPW] = {xv.x, xv.y, xv.z, xv.w};
            #pragma unroll
            for (int r = 0; r < RPW; ++r) { aA[r] += xq[r] * w.x; aB[r] += xq[r] * w.y; }
        }
        {
            const float bbx = s->b1[c0], bby = s->b1[c1];
            #pragma unroll
            for (int r = 0; r < RPW; ++r) {
                hT[c0][r] = gelu_exact(aA[r] + bbx);
                hT[c1][r] = gelu_exact(aB[r] + bby);
            }
        }
        __syncwarp();

        // ---- layer 2: h[4,64] @ W2[64,64] ----
        #pragma unroll
        for (int r = 0; r < RPW; ++r) { aA[r] = 0.f; aB[r] = 0.f; }
        #pragma unroll 4
        for (int k = 0; k < HID; ++k) {
            const float4 hv = *reinterpret_cast<const float4*>(hT[k]);
            const float2 w  = *reinterpret_cast<const float2*>(&s->W2[k * HID + c0]);
            const float hq[RPW] = {hv.x, hv.y, hv.z, hv.w};
            #pragma unroll
            for (int r = 0; r < RPW; ++r) { aA[r] += hq[r] * w.x; aB[r] += hq[r] * w.y; }
        }
        __syncwarp();   // everyone done reading hT before overwrite
        {
            const float bbx = s->b2[c0], bby = s->b2[c1];
            #pragma unroll
            for (int r = 0; r < RPW; ++r) {
                hT[c0][r] = gelu_exact(aA[r] + bbx);
                hT[c1][r] = gelu_exact(aB[r] + bby);
            }
        }
        __syncwarp();

        // ---- layer 3: logits = h2[4,64] @ W3[64,64] + b3 ----
        #pragma unroll
        for (int r = 0; r < RPW; ++r) { aA[r] = 0.f; aB[r] = 0.f; }
        #pragma unroll 4
        for (int k = 0; k < HID; ++k) {
            const float4 hv = *reinterpret_cast<const float4*>(hT[k]);
            const float2 w  = *reinterpret_cast<const float2*>(&s->W3[k * KEXP + c0]);
            const float hq[RPW] = {hv.x, hv.y, hv.z, hv.w};
            #pragma unroll
            for (int r = 0; r < RPW; ++r) { aA[r] += hq[r] * w.x; aB[r] += hq[r] * w.y; }
        }
        __syncwarp();   // hT reused next tile iteration
        const float b3x = s->b3[c0], b3y = s->b3[c1];

        // ---- epilogue per row: top-8 mask + softmax ----
        #pragma unroll
        for (int r = 0; r < RPW; ++r) {
            const int row = row0 + r;
            const float v0 = aA[r] + b3x;
            const float v1 = aB[r] + b3y;
            float w0 = v0, w1 = v1;
            bool  s0 = false, s1 = false;
            float vmax = 0.f;
            #pragma unroll
            for (int it = 0; it < TOPK; ++it) {
                const float m = warp_max(fmaxf(w0, w1));
                if (it == 0) vmax = m;
                int cand = KEXP;                 // smallest-column tie-break (jax top_k order)
                if (w1 == m) cand = c1;
                if (w0 == m) cand = c0;
                const int cmin = warp_min_i(cand);
                if (cand == cmin && cand < KEXP) {
                    if (cand == c0) { s0 = true; w0 = -INFINITY; }
                    else            { s1 = true; w1 = -INFINITY; }
                }
            }
            const float e0 = s0 ? expf(v0 - vmax) : 0.f;
            const float e1 = s1 ? expf(v1 - vmax) : 0.f;
            const float inv = 1.0f / warp_sum(e0 + e1);
            reinterpret_cast<float2*>(out)[row * 32 + lane] = make_float2(e0 * inv, e1 * inv);
        }
    }
}

extern "C" void kernel_launch(void* const* d_in, const int* in_sizes, int n_in,
                              void* d_out, int out_size)
{
    const float* hist   = (const float*)d_in[0];
    const float* num    = (const float*)d_in[1];
    const int*   cat    = (const int*)  d_in[2];
    const int*   region = (const int*)  d_in[3];
    const float* catT   = (const float*)d_in[4];
    const float* regT   = (const float*)d_in[5];
    const float* W1     = (const float*)d_in[6];
    const float* b1     = (const float*)d_in[7];
    const float* W2     = (const float*)d_in[8];
    const float* b2     = (const float*)d_in[9];
    const float* W3     = (const float*)d_in[10];
    const float* b3     = (const float*)d_in[11];
    float* out = (float*)d_out;

    cudaFuncSetAttribute(gating_kernel,
                         cudaFuncAttributeMaxDynamicSharedMemorySize,
                         (int)sizeof(Smem));
    gating_kernel<<<592, THREADS, sizeof(Smem)>>>(
        hist, num, cat, region, catT, regT, W1, b1, W2, b2, W3, b3, out);
}

// round 3
// speedup vs baseline: 1.0888x; 1.0879x over previous
#include <cuda_runtime.h>
#include <math.h>

#define B_ROWS   524288
#define HIST     50
#define NUMD     32
#define NCAT     8
#define CATD     16
#define REGD     32
#define INDIM    242          // 50 + 32 + 128 + 32
#define HID      64
#define KEXP     64
#define TOPK     8
#define HASHB    32768
#define GEOB     4096

#define THREADS   256
#define TILE_ROWS 128
#define XS        130                    // XT row stride in floats (even, !=0 mod 4 friendly)
#define NTILES    (B_ROWS / TILE_ROWS)   // 4096

// ---- smem layout: weights + one X/H scratch (aliased across layers) ----
struct __align__(16) Smem {
    float W1[INDIM * HID];    // 61952 B
    float W2[HID * HID];      // 16384 B
    float W3[HID * KEXP];     // 16384 B
    float b1[HID], b2[HID], b3[KEXP];
    float XH[INDIM * XS];     // 125840 B : XT, then HT (rows 0-63), H2T (rows 64-127)
};                            // total ~221.3 KB

// ---- packed f32x2 helpers (sm_103a FFMA2 path, bit-identical fp32 math) ----
__device__ __forceinline__ unsigned long long pk2(float lo, float hi) {
    unsigned long long r;
    asm("mov.b64 %0, {%1, %2};" : "=l"(r) : "f"(lo), "f"(hi));
    return r;
}
__device__ __forceinline__ void upk2(unsigned long long p, float& lo, float& hi) {
    asm("mov.b64 {%0, %1}, %2;" : "=f"(lo), "=f"(hi) : "l"(p));
}
__device__ __forceinline__ void fma2(unsigned long long& d,
                                     unsigned long long a, unsigned long long b) {
    asm("fma.rn.f32x2 %0, %1, %2, %0;" : "+l"(d) : "l"(a), "l"(b));
}

__device__ __forceinline__ float gelu_exact(float x) {
    return 0.5f * x * (1.0f + erff(x * 0.70710678118654752440f));
}

// ---- register-tiled GEMM: C[4 rows][8 cols] per thread, A transposed in smem ----
template<int K>
__device__ __forceinline__ void gemm_rt(const float* __restrict__ AT,   // [K][XS]
                                        const float* __restrict__ Wm,   // [K][64]
                                        int cg8, int rg4,
                                        unsigned long long acc[4][4])   // [colpair][row]
{
    #pragma unroll
    for (int pp = 0; pp < 4; ++pp)
        #pragma unroll
        for (int r = 0; r < 4; ++r) acc[pp][r] = 0ull;

    #pragma unroll 2
    for (int k = 0; k < K; ++k) {
        const float2 x01 = *reinterpret_cast<const float2*>(&AT[k * XS + rg4]);
        const float2 x23 = *reinterpret_cast<const float2*>(&AT[k * XS + rg4 + 2]);
        const unsigned long long* wr =
            reinterpret_cast<const unsigned long long*>(&Wm[k * 64 + cg8]);
        const unsigned long long w0 = wr[0], w1 = wr[1], w2 = wr[2], w3 = wr[3];
        const unsigned long long xb[4] = { pk2(x01.x, x01.x), pk2(x01.y, x01.y),
                                           pk2(x23.x, x23.x), pk2(x23.y, x23.y) };
        #pragma unroll
        for (int r = 0; r < 4; ++r) {
            fma2(acc[0][r], w0, xb[r]);
            fma2(acc[1][r], w1, xb[r]);
            fma2(acc[2][r], w2, xb[r]);
            fma2(acc[3][r], w3, xb[r]);
        }
    }
}

// gelu(acc + bias) -> DST[col][row] (transposed store for next layer)
__device__ __forceinline__ void act_store(const unsigned long long acc[4][4],
                                          const float* __restrict__ tb,  // 8 biases
                                          float* __restrict__ DST, int cg8, int rg4)
{
    #pragma unroll
    for (int pp = 0; pp < 4; ++pp) {
        float lo[4], hi[4];
        #pragma unroll
        for (int r = 0; r < 4; ++r) upk2(acc[pp][r], lo[r], hi[r]);
        float g0[4], g1[4];
        #pragma unroll
        for (int r = 0; r < 4; ++r) {
            g0[r] = gelu_exact(lo[r] + tb[2 * pp]);
            g1[r] = gelu_exact(hi[r] + tb[2 * pp + 1]);
        }
        float* d0 = &DST[(cg8 + 2 * pp) * XS + rg4];
        float* d1 = &DST[(cg8 + 2 * pp + 1) * XS + rg4];
        *reinterpret_cast<float2*>(d0)     = make_float2(g0[0], g0[1]);
        *reinterpret_cast<float2*>(d0 + 2) = make_float2(g0[2], g0[3]);
        *reinterpret_cast<float2*>(d1)     = make_float2(g1[0], g1[1]);
        *reinterpret_cast<float2*>(d1 + 2) = make_float2(g1[2], g1[3]);
    }
}

__global__ __launch_bounds__(THREADS)
void gating_kernel(const float* __restrict__ hist,
                   const float* __restrict__ num,
                   const int*   __restrict__ cat,
                   const int*   __restrict__ region,
                   const float* __restrict__ catT,
                   const float* __restrict__ regT,
                   const float* __restrict__ W1, const float* __restrict__ b1,
                   const float* __restrict__ W2, const float* __restrict__ b2,
                   const float* __restrict__ W3, const float* __restrict__ b3,
                   float* __restrict__ out)
{
    extern __shared__ float smem_raw[];
    Smem* s = reinterpret_cast<Smem*>(smem_raw);
    const int tid = threadIdx.x;

    for (int i = tid; i < INDIM * HID; i += THREADS) s->W1[i] = W1[i];
    for (int i = tid; i < HID * HID;   i += THREADS) s->W2[i] = W2[i];
    for (int i = tid; i < HID * KEXP;  i += THREADS) s->W3[i] = W3[i];
    if (tid < HID) { s->b1[tid] = b1[tid]; s->b2[tid] = b2[tid]; s->b3[tid] = b3[tid]; }
    __syncthreads();

    const int lane = tid & 31;
    const int warp = tid >> 5;      // 8 warps, 16 gather rows each
    const int cg   = tid & 7;       // column group: cols cg*8..cg*8+7
    const int rg   = tid >> 3;      // row group:    rows rg*4..rg*4+3
    const int cg8  = cg * 8;
    const int rg4  = rg * 4;

    float* XT  = s->XH;
    float* HT  = s->XH;                 // alias: rows 0-63 region
    float* H2T = s->XH + HID * XS;      // alias: rows 64-127 region

    float tb1[8], tb2[8], tb3[8];
    #pragma unroll
    for (int c = 0; c < 8; ++c) {
        tb1[c] = s->b1[cg8 + c];
        tb2[c] = s->b2[cg8 + c];
        tb3[c] = s->b3[cg8 + c];
    }

    for (int tile = blockIdx.x; tile < NTILES; tile += gridDim.x) {
        const int rbase = tile * TILE_ROWS;

        // ---- gather: build XT[k][local_row], conflict-free scalar STS ----
        {
            const int wrow = warp * 16;
            #pragma unroll 2
            for (int rr = 0; rr < 16; ++rr) {
                const int lr  = wrow + rr;
                const int row = rbase + lr;
                XT[lane * XS + lr] = hist[row * HIST + lane];
                if (lane < HIST - 32)
                    XT[(32 + lane) * XS + lr] = hist[row * HIST + 32 + lane];
                XT[(HIST + lane) * XS + lr] = num[row * NUMD + lane];
                #pragma unroll
                for (int i = 0; i < 4; ++i) {
                    const int t = lane + 32 * i;
                    const int j = t >> 4, d = t & 15;
                    int idx = cat[row * NCAT + j];
                    idx = min(max(idx, 0), HASHB - 1);
                    XT[(HIST + NUMD + t) * XS + lr] = catT[(j * HASHB + idx) * CATD + d];
                }
                int rid = region[row];
                rid = min(max(rid, 0), GEOB - 1);
                XT[(HIST + NUMD + NCAT * CATD + lane) * XS + lr] = regT[rid * REGD + lane];
            }
        }
        __syncthreads();

        unsigned long long acc[4][4];

        // ---- layer 1 ----
        gemm_rt<INDIM>(XT, s->W1, cg8, rg4, acc);
        __syncthreads();                         // all XT reads done
        act_store(acc, tb1, HT, cg8, rg4);
        __syncthreads();                         // HT ready

        // ---- layer 2 ----
        gemm_rt<HID>(HT, s->W2, cg8, rg4, acc);
        act_store(acc, tb2, H2T, cg8, rg4);      // disjoint from HT reads
        __syncthreads();                         // H2T ready

        // ---- layer 3 ----
        gemm_rt<HID>(H2T, s->W3, cg8, rg4, acc);
        __syncthreads();                         // H2T reads done; next gather may overwrite

        // ---- epilogue: per-row top-8 mask + softmax over 8-lane group ----
        #pragma unroll
        for (int r = 0; r < 4; ++r) {
            float v[8];
            #pragma unroll
            for (int pp = 0; pp < 4; ++pp) {
                float lo, hi; upk2(acc[pp][r], lo, hi);
                v[2 * pp]     = lo + tb3[2 * pp];
                v[2 * pp + 1] = hi + tb3[2 * pp + 1];
            }
            float w[8];
            #pragma unroll
            for (int c = 0; c < 8; ++c) w[c] = v[c];
            unsigned selm = 0u;
            float vmax = 0.f;
            #pragma unroll
            for (int it = 0; it < TOPK; ++it) {
                float bv = w[0]; int bc = 0;
                #pragma unroll
                for (int c = 1; c < 8; ++c)
                    if (w[c] > bv) { bv = w[c]; bc = c; }     // strict > keeps lowest col
                int bcol = cg8 + bc;
                #pragma unroll
                for (int o = 1; o <= 4; o <<= 1) {
                    const float ov = __shfl_xor_sync(0xffffffffu, bv, o);
                    const int   oc = __shfl_xor_sync(0xffffffffu, bcol, o);
                    if (ov > bv || (ov == bv && oc < bcol)) { bv = ov; bcol = oc; }
                }
                if (it == 0) vmax = bv;
                if ((bcol >> 3) == cg) {
                    const int c = bcol & 7;
                    selm |= 1u << c;
                    #pragma unroll
                    for (int cc = 0; cc < 8; ++cc)
                        if (cc == c) w[cc] = -INFINITY;
                }
            }
            float e[8], ssum = 0.f;
            #pragma unroll
            for (int c = 0; c < 8; ++c) {
                e[c] = ((selm >> c) & 1u) ? expf(v[c] - vmax) : 0.f;
                ssum += e[c];
            }
            #pragma unroll
            for (int o = 1; o <= 4; o <<= 1)
                ssum += __shfl_xor_sync(0xffffffffu, ssum, o);
            const float inv = 1.0f / ssum;
            float4* op = reinterpret_cast<float4*>(
                &out[(size_t)(rbase + rg4 + r) * KEXP + cg8]);
            op[0] = make_float4(e[0] * inv, e[1] * inv, e[2] * inv, e[3] * inv);
            op[1] = make_float4(e[4] * inv, e[5] * inv, e[6] * inv, e[7] * inv);
        }
    }
}

extern "C" void kernel_launch(void* const* d_in, const int* in_sizes, int n_in,
                              void* d_out, int out_size)
{
    const float* hist   = (const float*)d_in[0];
    const float* num    = (const float*)d_in[1];
    const int*   cat    = (const int*)  d_in[2];
    const int*   region = (const int*)  d_in[3];
    const float* catT   = (const float*)d_in[4];
    const float* regT   = (const float*)d_in[5];
    const float* W1     = (const float*)d_in[6];
    const float* b1     = (const float*)d_in[7];
    const float* W2     = (const float*)d_in[8];
    const float* b2     = (const float*)d_in[9];
    const float* W3     = (const float*)d_in[10];
    const float* b3     = (const float*)d_in[11];
    float* out = (float*)d_out;

    cudaFuncSetAttribute(gating_kernel,
                         cudaFuncAttributeMaxDynamicSharedMemorySize,
                         (int)sizeof(Smem));
    gating_kernel<<<148, THREADS, sizeof(Smem)>>>(
        hist, num, cat, region, catT, regT, W1, b1, W2, b2, W3, b3, out);
}

// round 7
// speedup vs baseline: 1.5161x; 1.3924x over previous
#include <cuda_runtime.h>
#include <math.h>
#include <stdint.h>

#define HIST     50
#define NUMD     32
#define NCAT     8
#define CATD     16
#define REGD     32
#define INDIM    242
#define HID      64
#define KEXP     64
#define TOPK     8
#define HASHB    32768
#define GEOB     4096
#define B_ROWS   524288

#define THREADS  256
#define TILE_M   128
#define NTILES   (B_ROWS / TILE_M)   // 4096
#define XS       132                  // floats per k-row (16B-aligned stride, conflict-free)
#define LGS      68                   // logit scratch row stride (floats)

// ---- SMEM layout (byte offsets). H/H2/logits alias the X region. ----
#define OFF_X      0                 // 242*132*4 = 127776
#define OFF_H      0                 //  64*132*4 = 33792 (X dead after L1)
#define OFF_H2     34816             //  33792
#define OFF_LG     69632             // 128*68*4 = 34816 (ends 104448 < 127776)
#define OFF_W1     127872            // 242*64*4 = 61952
#define OFF_W2     189824            // 16384
#define OFF_W3     206208            // 16384
#define OFF_B1     222592
#define OFF_B2     222848
#define OFF_B3     223104
#define SMEM_TOTAL 223360

// ---- packed f32x2 helpers (FFMA2: bit-identical fp32 math, 2 FMA/instr) ----
__device__ __forceinline__ unsigned long long pk2(float lo, float hi) {
    unsigned long long r;
    asm("mov.b64 %0, {%1, %2};" : "=l"(r) : "f"(lo), "f"(hi));
    return r;
}
__device__ __forceinline__ void upk2(unsigned long long p, float& lo, float& hi) {
    asm("mov.b64 {%0, %1}, %2;" : "=f"(lo), "=f"(hi) : "l"(p));
}
__device__ __forceinline__ void fma2(unsigned long long& d,
                                     unsigned long long a, unsigned long long b) {
    asm("fma.rn.f32x2 %0, %1, %2, %0;" : "+l"(d) : "l"(a), "l"(b));
}

__device__ __forceinline__ float gelu_exact(float x) {
    return 0.5f * x * (1.0f + erff(x * 0.70710678118654752440f));
}

// ---- register-tiled GEMM: thread = 8 rows x 4 cols, k ascending (bitwise fp32) ----
// A: k-major [K][XS]; W: k-major [K][64]. acc[rowpair][col] packed f32x2 over rows.
template<int K>
__device__ __forceinline__ void gemm_rt(const float* __restrict__ A,
                                        const float* __restrict__ W,
                                        int r0, int c0,
                                        unsigned long long acc[4][4]) {
    #pragma unroll
    for (int rp = 0; rp < 4; ++rp)
        #pragma unroll
        for (int c = 0; c < 4; ++c) acc[rp][c] = 0ull;

    const float* a = A + r0;
    const float* w = W + c0;
    #pragma unroll 2
    for (int k = 0; k < K; ++k) {
        const float4 x0 = *reinterpret_cast<const float4*>(a);
        const float4 x1 = *reinterpret_cast<const float4*>(a + 4);
        const float4 wv = *reinterpret_cast<const float4*>(w);
        const unsigned long long xp[4] = { pk2(x0.x, x0.y), pk2(x0.z, x0.w),
                                           pk2(x1.x, x1.y), pk2(x1.z, x1.w) };
        const unsigned long long wd[4] = { pk2(wv.x, wv.x), pk2(wv.y, wv.y),
                                           pk2(wv.z, wv.z), pk2(wv.w, wv.w) };
        #pragma unroll
        for (int rp = 0; rp < 4; ++rp) {
            fma2(acc[rp][0], xp[rp], wd[0]);
            fma2(acc[rp][1], xp[rp], wd[1]);
            fma2(acc[rp][2], xp[rp], wd[2]);
            fma2(acc[rp][3], xp[rp], wd[3]);
        }
        a += XS; w += 64;
    }
}

// gelu(acc + bias) -> k-major DST[c][r] for the next layer
__device__ __forceinline__ void act_store(const unsigned long long acc[4][4],
                                          float4 bv, float* __restrict__ DST,
                                          int r0, int c0) {
    const float bb[4] = { bv.x, bv.y, bv.z, bv.w };
    #pragma unroll
    for (int c = 0; c < 4; ++c) {
        float g[8];
        #pragma unroll
        for (int rp = 0; rp < 4; ++rp) {
            float lo, hi; upk2(acc[rp][c], lo, hi);
            g[2 * rp]     = gelu_exact(lo + bb[c]);
            g[2 * rp + 1] = gelu_exact(hi + bb[c]);
        }
        float* d = DST + (c0 + c) * XS + r0;
        *reinterpret_cast<float4*>(d)     = make_float4(g[0], g[1], g[2], g[3]);
        *reinterpret_cast<float4*>(d + 4) = make_float4(g[4], g[5], g[6], g[7]);
    }
}

__global__ __launch_bounds__(THREADS, 1)
void gating_kernel(const float* __restrict__ hist,
                   const float* __restrict__ num,
                   const int*   __restrict__ cat,
                   const int*   __restrict__ region,
                   const float* __restrict__ catT,
                   const float* __restrict__ regT,
                   const float* __restrict__ W1, const float* __restrict__ b1,
                   const float* __restrict__ W2, const float* __restrict__ b2,
                   const float* __restrict__ W3, const float* __restrict__ b3,
                   float* __restrict__ out)
{
    extern __shared__ __align__(16) char sm[];
    float* smf = reinterpret_cast<float*>(sm);
    const int tid  = threadIdx.x;
    const int wid  = tid >> 5;
    const int lane = tid & 31;

    float* sx  = (float*)(sm + OFF_X);
    float* sh  = (float*)(sm + OFF_H);
    float* sh2 = (float*)(sm + OFF_H2);
    float* slg = (float*)(sm + OFF_LG);
    float* sw1 = (float*)(sm + OFF_W1);
    float* sw2 = (float*)(sm + OFF_W2);
    float* sw3 = (float*)(sm + OFF_W3);

    // ---- stage weights (k-major, direct copy) + biases ----
    for (int i = tid; i < INDIM * 64 / 4; i += THREADS)
        ((float4*)sw1)[i] = ((const float4*)W1)[i];
    for (int i = tid; i < 64 * 64 / 4; i += THREADS) {
        ((float4*)sw2)[i] = ((const float4*)W2)[i];
        ((float4*)sw3)[i] = ((const float4*)W3)[i];
    }
    if (tid < 64) {
        ((float*)(sm + OFF_B1))[tid] = b1[tid];
        ((float*)(sm + OFF_B2))[tid] = b2[tid];
        ((float*)(sm + OFF_B3))[tid] = b3[tid];
    }
    __syncthreads();

    // GEMM thread mapping: warp = 32 rows x 32 cols; thread = 8 rows x 4 cols
    const int warpRow = (wid & 3) * 32;
    const int warpCol = (wid >> 2) * 32;
    const int rsub = lane >> 3;        // 0..3
    const int csub = lane & 7;         // 0..7
    const int r0 = warpRow + rsub * 8;
    const int c0 = warpCol + csub * 4;

    const float4 b1v = *(const float4*)((const float*)(sm + OFF_B1) + c0);
    const float4 b2v = *(const float4*)((const float*)(sm + OFF_B2) + c0);
    const float4 b3v = *(const float4*)((const float*)(sm + OFF_B3) + c0);

    for (int tile = blockIdx.x; tile < NTILES; tile += gridDim.x) {
        const int rbase = tile * TILE_M;

        // ---- gather -> X[k][r] (k-major); warp = 16 rows, lanes spread k ----
        {
            const int wrow = wid * 16;
            #pragma unroll 2
            for (int rr = 0; rr < 16; ++rr) {
                const int lr = wrow + rr;
                const size_t row = (size_t)(rbase + lr);
                sx[lane * XS + lr] = hist[row * HIST + lane];
                if (lane < HIST - 32)
                    sx[(32 + lane) * XS + lr] = hist[row * HIST + 32 + lane];
                sx[(HIST + lane) * XS + lr] = num[row * NUMD + lane];
                #pragma unroll
                for (int i = 0; i < 4; ++i) {
                    const int t = lane + 32 * i;
                    const int j = t >> 4, d = t & 15;
                    int idx = cat[row * NCAT + j];
                    idx = min(max(idx, 0), HASHB - 1);
                    sx[(HIST + NUMD + t) * XS + lr] = catT[(size_t)(j * HASHB + idx) * CATD + d];
                }
                int rid = region[row];
                rid = min(max(rid, 0), GEOB - 1);
                sx[(HIST + NUMD + NCAT * CATD + lane) * XS + lr] = regT[(size_t)rid * REGD + lane];
            }
        }
        __syncthreads();

        unsigned long long acc[4][4];

        // ---- layer 1 (K=242) ----
        gemm_rt<INDIM>(sx, sw1, r0, c0, acc);
        __syncthreads();                       // all X reads done (H aliases X)
        act_store(acc, b1v, sh, r0, c0);
        __syncthreads();                       // H ready

        // ---- layer 2 (K=64) ----
        gemm_rt<HID>(sh, sw2, r0, c0, acc);
        act_store(acc, b2v, sh2, r0, c0);      // H2 disjoint from H: no sync needed
        __syncthreads();                       // H2 ready

        // ---- layer 3 (K=64): dump logits (+bias) to scratch ----
        gemm_rt<HID>(sh2, sw3, r0, c0, acc);
        {
            const float bb[4] = { b3v.x, b3v.y, b3v.z, b3v.w };
            #pragma unroll
            for (int rp = 0; rp < 4; ++rp) {
                float lo[4], hi[4];
                #pragma unroll
                for (int c = 0; c < 4; ++c) { upk2(acc[rp][c], lo[c], hi[c]); }
                float* d0 = slg + (r0 + 2 * rp)     * LGS + c0;
                float* d1 = slg + (r0 + 2 * rp + 1) * LGS + c0;
                *reinterpret_cast<float4*>(d0) =
                    make_float4(lo[0] + bb[0], lo[1] + bb[1], lo[2] + bb[2], lo[3] + bb[3]);
                *reinterpret_cast<float4*>(d1) =
                    make_float4(hi[0] + bb[0], hi[1] + bb[1], hi[2] + bb[2], hi[3] + bb[3]);
            }
        }
        __syncthreads();

        // ---- per-row top-8 + softmax (threads 0..127, one row each) ----
        if (tid < TILE_M) {
            float v[KEXP];
            #pragma unroll
            for (int g = 0; g < 16; ++g) {
                const float4 t = *reinterpret_cast<const float4*>(slg + tid * LGS + g * 4);
                v[4 * g] = t.x; v[4 * g + 1] = t.y; v[4 * g + 2] = t.z; v[4 * g + 3] = t.w;
            }
            unsigned long long used = 0ull;
            float sv[TOPK]; int si[TOPK];
            #pragma unroll
            for (int it = 0; it < TOPK; ++it) {
                float bv = -INFINITY; int bi = 0;
                #pragma unroll
                for (int i = 0; i < KEXP; ++i) {
                    const bool take = (((used >> i) & 1ull) == 0ull) && (v[i] > bv);
                    if (take) { bv = v[i]; bi = i; }   // strict > : lowest index on ties
                }
                used |= 1ull << bi; sv[it] = bv; si[it] = bi;
            }
            const float vmax = sv[0];
            float e[TOPK], ssum = 0.f;
            #pragma unroll
            for (int t = 0; t < TOPK; ++t) { e[t] = expf(sv[t] - vmax); ssum += e[t]; }
            const float inv = 1.0f / ssum;
            // write alpha row back into scratch (dense, mostly zeros)
            #pragma unroll
            for (int g = 0; g < 16; ++g)
                *reinterpret_cast<float4*>(slg + tid * LGS + g * 4) =
                    make_float4(0.f, 0.f, 0.f, 0.f);
            #pragma unroll
            for (int t = 0; t < TOPK; ++t) slg[tid * LGS + si[t]] = e[t] * inv;
        }
        __syncthreads();

        // ---- coalesced copy scratch -> out ----
        {
            float4* obase = reinterpret_cast<float4*>(out + (size_t)rbase * KEXP);
            #pragma unroll
            for (int j = 0; j < 8; ++j) {
                const int idx = tid + j * THREADS;          // 0..2047 float4s
                const int r = idx >> 4, cq = idx & 15;
                obase[idx] = *reinterpret_cast<const float4*>(slg + r * LGS + cq * 4);
            }
        }
        __syncthreads();   // scratch/X region free for next tile's gather
    }
}

extern "C" void kernel_launch(void* const* d_in, const int* in_sizes, int n_in,
                              void* d_out, int out_size)
{
    const float* hist   = (const float*)d_in[0];
    const float* num    = (const float*)d_in[1];
    const int*   cat    = (const int*)  d_in[2];
    const int*   region = (const int*)  d_in[3];
    const float* catT   = (const float*)d_in[4];
    const float* regT   = (const float*)d_in[5];
    const float* W1     = (const float*)d_in[6];
    const float* b1     = (const float*)d_in[7];
    const float* W2     = (const float*)d_in[8];
    const float* b2     = (const float*)d_in[9];
    const float* W3     = (const float*)d_in[10];
    const float* b3     = (const float*)d_in[11];
    float* out = (float*)d_out;

    cudaFuncSetAttribute(gating_kernel,
                         cudaFuncAttributeMaxDynamicSharedMemorySize, SMEM_TOTAL);
    gating_kernel<<<148, THREADS, SMEM_TOTAL>>>(
        hist, num, cat, region, catT, regT, W1, b1, W2, b2, W3, b3, out);
}

// round 8
// speedup vs baseline: 1.7349x; 1.1443x over previous
#include <cuda_runtime.h>
#include <math.h>
#include <stdint.h>

#define HIST     50
#define NUMD     32
#define NCAT     8
#define CATD     16
#define REGD     32
#define INDIM    242
#define HID      64
#define KEXP     64
#define TOPK     8
#define HASHB    32768
#define GEOB     4096
#define B_ROWS   524288

#define THREADS  512
#define NWARP    16
#define TILE_M   128
#define NTILES   (B_ROWS / TILE_M)   // 4096
#define XS       132                  // floats per k-row (16B-aligned stride)
#define LGS      68                   // logit scratch row stride (floats)

// ---- SMEM layout (byte offsets). H/H2/logits alias the X region. ----
#define OFF_X      0                 // 242*132*4 = 127776
#define OFF_H      0                 //  64*132*4 = 33792 (X dead after L1)
#define OFF_H2     34816             //  33792
#define OFF_LG     69632             // 128*68*4 = 34816 (ends 104448 < 127776)
#define OFF_W1     127872            // 242*64*4 = 61952
#define OFF_W2     189824            // 16384
#define OFF_W3     206208            // 16384
#define OFF_B1     222592
#define OFF_B2     222848
#define OFF_B3     223104
#define SMEM_TOTAL 223360

// ---- packed f32x2 helpers (FFMA2: bit-identical fp32 math, 2 FMA/instr) ----
__device__ __forceinline__ unsigned long long pk2(float lo, float hi) {
    unsigned long long r;
    asm("mov.b64 %0, {%1, %2};" : "=l"(r) : "f"(lo), "f"(hi));
    return r;
}
__device__ __forceinline__ void upk2(unsigned long long p, float& lo, float& hi) {
    asm("mov.b64 {%0, %1}, %2;" : "=f"(lo), "=f"(hi) : "l"(p));
}
__device__ __forceinline__ void fma2(unsigned long long& d,
                                     unsigned long long a, unsigned long long b) {
    asm("fma.rn.f32x2 %0, %1, %2, %0;" : "+l"(d) : "l"(a), "l"(b));
}

__device__ __forceinline__ float gelu_exact(float x) {
    return 0.5f * x * (1.0f + erff(x * 0.70710678118654752440f));
}

// ---- register-tiled GEMM: thread = 8 rows x 2 cols, k ascending (bitwise fp32) ----
// A: k-major [K][XS]; W: k-major [K][64]. acc[rowpair][col] packed f32x2 over rows.
template<int K>
__device__ __forceinline__ void gemm_rt(const float* __restrict__ A,
                                        const float* __restrict__ W,
                                        int r0, int c0,
                                        unsigned long long acc[4][2]) {
    #pragma unroll
    for (int rp = 0; rp < 4; ++rp) {
        acc[rp][0] = 0ull; acc[rp][1] = 0ull;
    }
    const float* a = A + r0;
    const float* w = W + c0;
    #pragma unroll 2
    for (int k = 0; k < K; ++k) {
        const float4 x0 = *reinterpret_cast<const float4*>(a);
        const float4 x1 = *reinterpret_cast<const float4*>(a + 4);
        const float2 wv = *reinterpret_cast<const float2*>(w);
        const unsigned long long xp[4] = { pk2(x0.x, x0.y), pk2(x0.z, x0.w),
                                           pk2(x1.x, x1.y), pk2(x1.z, x1.w) };
        const unsigned long long wd0 = pk2(wv.x, wv.x);
        const unsigned long long wd1 = pk2(wv.y, wv.y);
        #pragma unroll
        for (int rp = 0; rp < 4; ++rp) {
            fma2(acc[rp][0], xp[rp], wd0);
            fma2(acc[rp][1], xp[rp], wd1);
        }
        a += XS; w += 64;
    }
}

// gelu(acc + bias) -> k-major DST[c][r] for the next layer
__device__ __forceinline__ void act_store(const unsigned long long acc[4][2],
                                          float2 bv, float* __restrict__ DST,
                                          int r0, int c0) {
    const float bb[2] = { bv.x, bv.y };
    #pragma unroll
    for (int c = 0; c < 2; ++c) {
        float g[8];
        #pragma unroll
        for (int rp = 0; rp < 4; ++rp) {
            float lo, hi; upk2(acc[rp][c], lo, hi);
            g[2 * rp]     = gelu_exact(lo + bb[c]);
            g[2 * rp + 1] = gelu_exact(hi + bb[c]);
        }
        float* d = DST + (c0 + c) * XS + r0;
        *reinterpret_cast<float4*>(d)     = make_float4(g[0], g[1], g[2], g[3]);
        *reinterpret_cast<float4*>(d + 4) = make_float4(g[4], g[5], g[6], g[7]);
    }
}

__global__ __launch_bounds__(THREADS, 1)
void gating_kernel(const float* __restrict__ hist,
                   const float* __restrict__ num,
                   const int*   __restrict__ cat,
                   const int*   __restrict__ region,
                   const float* __restrict__ catT,
                   const float* __restrict__ regT,
                   const float* __restrict__ W1, const float* __restrict__ b1,
                   const float* __restrict__ W2, const float* __restrict__ b2,
                   const float* __restrict__ W3, const float* __restrict__ b3,
                   float* __restrict__ out)
{
    extern __shared__ __align__(16) char sm[];
    const int tid  = threadIdx.x;
    const int wid  = tid >> 5;
    const int lane = tid & 31;

    float* sx  = (float*)(sm + OFF_X);
    float* sh  = (float*)(sm + OFF_H);
    float* sh2 = (float*)(sm + OFF_H2);
    float* slg = (float*)(sm + OFF_LG);
    float* sw1 = (float*)(sm + OFF_W1);
    float* sw2 = (float*)(sm + OFF_W2);
    float* sw3 = (float*)(sm + OFF_W3);

    // ---- stage weights (k-major, direct copy) + biases ----
    for (int i = tid; i < INDIM * 64 / 4; i += THREADS)
        ((float4*)sw1)[i] = ((const float4*)W1)[i];
    for (int i = tid; i < 64 * 64 / 4; i += THREADS) {
        ((float4*)sw2)[i] = ((const float4*)W2)[i];
        ((float4*)sw3)[i] = ((const float4*)W3)[i];
    }
    if (tid < 64) {
        ((float*)(sm + OFF_B1))[tid] = b1[tid];
        ((float*)(sm + OFF_B2))[tid] = b2[tid];
        ((float*)(sm + OFF_B3))[tid] = b3[tid];
    }
    __syncthreads();

    // GEMM mapping: warp = 32 rows x 16 cols; thread = 8 rows x 2 cols
    const int warpRow = (wid & 3) * 32;
    const int warpCol = (wid >> 2) * 16;
    const int rsub = lane >> 3;        // 0..3
    const int csub = lane & 7;         // 0..7
    const int r0 = warpRow + rsub * 8;
    const int c0 = warpCol + csub * 2;

    const float2 b1v = *(const float2*)((const float*)(sm + OFF_B1) + c0);
    const float2 b2v = *(const float2*)((const float*)(sm + OFF_B2) + c0);
    const float2 b3v = *(const float2*)((const float*)(sm + OFF_B3) + c0);

    for (int tile = blockIdx.x; tile < NTILES; tile += gridDim.x) {
        const int rbase = tile * TILE_M;

        // ---- gather -> X[k][r] (k-major); warp = 8 rows, lanes spread k ----
        {
            const int wrow = wid * 8;
            #pragma unroll 2
            for (int rr = 0; rr < 8; ++rr) {
                const int lr = wrow + rr;
                const size_t row = (size_t)(rbase + lr);
                sx[lane * XS + lr] = hist[row * HIST + lane];
                if (lane < HIST - 32)
                    sx[(32 + lane) * XS + lr] = hist[row * HIST + 32 + lane];
                sx[(HIST + lane) * XS + lr] = num[row * NUMD + lane];
                #pragma unroll
                for (int i = 0; i < 4; ++i) {
                    const int t = lane + 32 * i;
                    const int j = t >> 4, d = t & 15;
                    int idx = cat[row * NCAT + j];
                    idx = min(max(idx, 0), HASHB - 1);
                    sx[(HIST + NUMD + t) * XS + lr] = catT[(size_t)(j * HASHB + idx) * CATD + d];
                }
                int rid = region[row];
                rid = min(max(rid, 0), GEOB - 1);
                sx[(HIST + NUMD + NCAT * CATD + lane) * XS + lr] = regT[(size_t)rid * REGD + lane];
            }
        }
        __syncthreads();

        unsigned long long acc[4][2];

        // ---- layer 1 (K=242) ----
        gemm_rt<INDIM>(sx, sw1, r0, c0, acc);
        __syncthreads();                       // all X reads done (H aliases X)
        act_store(acc, b1v, sh, r0, c0);
        __syncthreads();                       // H ready

        // ---- layer 2 (K=64) ----
        gemm_rt<HID>(sh, sw2, r0, c0, acc);
        act_store(acc, b2v, sh2, r0, c0);      // H2 disjoint from H: no sync needed
        __syncthreads();                       // H2 ready

        // ---- layer 3 (K=64): dump logits (+bias) to scratch ----
        gemm_rt<HID>(sh2, sw3, r0, c0, acc);
        {
            const float bb[2] = { b3v.x, b3v.y };
            #pragma unroll
            for (int rp = 0; rp < 4; ++rp) {
                float lo[2], hi[2];
                upk2(acc[rp][0], lo[0], hi[0]);
                upk2(acc[rp][1], lo[1], hi[1]);
                float* d0 = slg + (r0 + 2 * rp)     * LGS + c0;
                float* d1 = slg + (r0 + 2 * rp + 1) * LGS + c0;
                *reinterpret_cast<float2*>(d0) = make_float2(lo[0] + bb[0], lo[1] + bb[1]);
                *reinterpret_cast<float2*>(d1) = make_float2(hi[0] + bb[0], hi[1] + bb[1]);
            }
        }
        __syncthreads();

        // ---- per-row top-8 + softmax (threads 0..127, one row each) ----
        if (tid < TILE_M) {
            float v[KEXP];
            #pragma unroll
            for (int g = 0; g < 16; ++g) {
                const float4 t = *reinterpret_cast<const float4*>(slg + tid * LGS + g * 4);
                v[4 * g] = t.x; v[4 * g + 1] = t.y; v[4 * g + 2] = t.z; v[4 * g + 3] = t.w;
            }
            unsigned long long used = 0ull;
            float sv[TOPK]; int si[TOPK];
            #pragma unroll
            for (int it = 0; it < TOPK; ++it) {
                float bv = -INFINITY; int bi = 0;
                #pragma unroll
                for (int i = 0; i < KEXP; ++i) {
                    const bool take = (((used >> i) & 1ull) == 0ull) && (v[i] > bv);
                    if (take) { bv = v[i]; bi = i; }   // strict > : lowest index on ties
                }
                used |= 1ull << bi; sv[it] = bv; si[it] = bi;
            }
            const float vmax = sv[0];
            float e[TOPK], ssum = 0.f;
            #pragma unroll
            for (int t = 0; t < TOPK; ++t) { e[t] = expf(sv[t] - vmax); ssum += e[t]; }
            const float inv = 1.0f / ssum;
            #pragma unroll
            for (int g = 0; g < 16; ++g)
                *reinterpret_cast<float4*>(slg + tid * LGS + g * 4) =
                    make_float4(0.f, 0.f, 0.f, 0.f);
            #pragma unroll
            for (int t = 0; t < TOPK; ++t) slg[tid * LGS + si[t]] = e[t] * inv;
        }
        __syncthreads();

        // ---- coalesced copy scratch -> out (2048 float4s, 4 per thread) ----
        {
            float4* obase = reinterpret_cast<float4*>(out + (size_t)rbase * KEXP);
            #pragma unroll
            for (int j = 0; j < 4; ++j) {
                const int idx = tid + j * THREADS;          // 0..2047
                const int r = idx >> 4, cq = idx & 15;
                obase[idx] = *reinterpret_cast<const float4*>(slg + r * LGS + cq * 4);
            }
        }
        __syncthreads();   // scratch/X region free for next tile's gather
    }
}

extern "C" void kernel_launch(void* const* d_in, const int* in_sizes, int n_in,
                              void* d_out, int out_size)
{
    const float* hist   = (const float*)d_in[0];
    const float* num    = (const float*)d_in[1];
    const int*   cat    = (const int*)  d_in[2];
    const int*   region = (const int*)  d_in[3];
    const float* catT   = (const float*)d_in[4];
    const float* regT   = (const float*)d_in[5];
    const float* W1     = (const float*)d_in[6];
    const float* b1     = (const float*)d_in[7];
    const float* W2     = (const float*)d_in[8];
    const float* b2     = (const float*)d_in[9];
    const float* W3     = (const float*)d_in[10];
    const float* b3     = (const float*)d_in[11];
    float* out = (float*)d_out;

    cudaFuncSetAttribute(gating_kernel,
                         cudaFuncAttributeMaxDynamicSharedMemorySize, SMEM_TOTAL);
    gating_kernel<<<148, THREADS, SMEM_TOTAL>>>(
        hist, num, cat, region, catT, regT, W1, b1, W2, b2, W3, b3, out);
}

// round 9
// speedup vs baseline: 1.7768x; 1.0242x over previous
#include <cuda_runtime.h>
#include <math.h>
#include <stdint.h>

#define HIST     50
#define NUMD     32
#define NCAT     8
#define CATD     16
#define REGD     32
#define INDIM    242
#define HID      64
#define KEXP     64
#define TOPK     8
#define HASHB    32768
#define GEOB     4096
#define B_ROWS   524288

#define THREADS  512
#define TILE_M   128
#define NTILES   (B_ROWS / TILE_M)   // 4096
#define XS       132                  // floats per k-row (16B-aligned stride)
#define LGS      68                   // logit scratch row stride (floats)

// ---- SMEM layout (byte offsets). H/H2/logits alias the X region. ----
#define OFF_X      0                 // 242*132*4 = 127776
#define OFF_H      0                 //  64*132*4 = 33792 (X dead after L1)
#define OFF_H2     34816             //  33792
#define OFF_LG     69632             // 128*68*4 = 34816 (ends 104448 < 127776)
#define OFF_W1     127872            // 242*64*4 = 61952
#define OFF_W2     189824            // 16384
#define OFF_W3     206208            // 16384
#define OFF_B1     222592
#define OFF_B2     222848
#define OFF_B3     223104
#define SMEM_TOTAL 223360

// ---- packed f32x2 helpers (FFMA2: bit-identical fp32 math, 2 FMA/instr) ----
__device__ __forceinline__ unsigned long long pk2(float lo, float hi) {
    unsigned long long r;
    asm("mov.b64 %0, {%1, %2};" : "=l"(r) : "f"(lo), "f"(hi));
    return r;
}
__device__ __forceinline__ void upk2(unsigned long long p, float& lo, float& hi) {
    asm("mov.b64 {%0, %1}, %2;" : "=f"(lo), "=f"(hi) : "l"(p));
}
__device__ __forceinline__ void fma2(unsigned long long& d,
                                     unsigned long long a, unsigned long long b) {
    asm("fma.rn.f32x2 %0, %1, %2, %0;" : "+l"(d) : "l"(a), "l"(b));
}

__device__ __forceinline__ float gelu_exact(float x) {
    return 0.5f * x * (1.0f + erff(x * 0.70710678118654752440f));
}

// ---- register-tiled GEMM: thread = 4 rows x 4 cols, k ascending (bitwise fp32) ----
// A: k-major [K][XS]; W: k-major [K][64].
// acc[r][cp] = packed f32x2 over col pair (c0+2cp, c0+2cp+1) for row r0+r.
// W pairs are read directly from smem as 64-bit values (no dup movs for W).
template<int K>
__device__ __forceinline__ void gemm_rt(const float* __restrict__ A,
                                        const float* __restrict__ W,
                                        int r0, int c0,
                                        unsigned long long acc[4][2]) {
    #pragma unroll
    for (int r = 0; r < 4; ++r) { acc[r][0] = 0ull; acc[r][1] = 0ull; }

    const float* a = A + r0;
    const float* w = W + c0;
    #pragma unroll 4
    for (int k = 0; k < K; ++k) {
        const float4 xv = *reinterpret_cast<const float4*>(a);
        const unsigned long long* wq = reinterpret_cast<const unsigned long long*>(w);
        const unsigned long long wp0 = wq[0];
        const unsigned long long wp1 = wq[1];
        const unsigned long long xd[4] = { pk2(xv.x, xv.x), pk2(xv.y, xv.y),
                                           pk2(xv.z, xv.z), pk2(xv.w, xv.w) };
        #pragma unroll
        for (int r = 0; r < 4; ++r) {
            fma2(acc[r][0], xd[r], wp0);
            fma2(acc[r][1], xd[r], wp1);
        }
        a += XS; w += 64;
    }
}

// gelu(acc + bias) -> k-major DST[c][r] for the next layer
__device__ __forceinline__ void act_store(const unsigned long long acc[4][2],
                                          float4 bv, float* __restrict__ DST,
                                          int r0, int c0) {
    float gv[4][4];   // [row][col]
    #pragma unroll
    for (int r = 0; r < 4; ++r) {
        upk2(acc[r][0], gv[r][0], gv[r][1]);
        upk2(acc[r][1], gv[r][2], gv[r][3]);
    }
    const float bb[4] = { bv.x, bv.y, bv.z, bv.w };
    #pragma unroll
    for (int r = 0; r < 4; ++r)
        #pragma unroll
        for (int c = 0; c < 4; ++c)
            gv[r][c] = gelu_exact(gv[r][c] + bb[c]);
    #pragma unroll
    for (int c = 0; c < 4; ++c)
        *reinterpret_cast<float4*>(DST + (c0 + c) * XS + r0) =
            make_float4(gv[0][c], gv[1][c], gv[2][c], gv[3][c]);
}

__global__ __launch_bounds__(THREADS, 1)
void gating_kernel(const float* __restrict__ hist,
                   const float* __restrict__ num,
                   const int*   __restrict__ cat,
                   const int*   __restrict__ region,
                   const float* __restrict__ catT,
                   const float* __restrict__ regT,
                   const float* __restrict__ W1, const float* __restrict__ b1,
                   const float* __restrict__ W2, const float* __restrict__ b2,
                   const float* __restrict__ W3, const float* __restrict__ b3,
                   float* __restrict__ out)
{
    extern __shared__ __align__(16) char sm[];
    const int tid  = threadIdx.x;
    const int wid  = tid >> 5;
    const int lane = tid & 31;

    float* sx  = (float*)(sm + OFF_X);
    float* sh  = (float*)(sm + OFF_H);
    float* sh2 = (float*)(sm + OFF_H2);
    float* slg = (float*)(sm + OFF_LG);
    float* sw1 = (float*)(sm + OFF_W1);
    float* sw2 = (float*)(sm + OFF_W2);
    float* sw3 = (float*)(sm + OFF_W3);

    // ---- stage weights (k-major, direct copy) + biases ----
    for (int i = tid; i < INDIM * 64 / 4; i += THREADS)
        ((float4*)sw1)[i] = ((const float4*)W1)[i];
    for (int i = tid; i < 64 * 64 / 4; i += THREADS) {
        ((float4*)sw2)[i] = ((const float4*)W2)[i];
        ((float4*)sw3)[i] = ((const float4*)W3)[i];
    }
    if (tid < 64) {
        ((float*)(sm + OFF_B1))[tid] = b1[tid];
        ((float*)(sm + OFF_B2))[tid] = b2[tid];
        ((float*)(sm + OFF_B3))[tid] = b3[tid];
    }
    __syncthreads();

    // GEMM mapping: warp = 16 rows x 32 cols; thread = 4 rows x 4 cols
    const int warpRow = (wid & 7) * 16;
    const int warpCol = (wid >> 3) * 32;
    const int r0 = warpRow + (lane & 3) * 4;
    const int c0 = warpCol + (lane >> 2) * 4;

    const float4 b1v = *(const float4*)((const float*)(sm + OFF_B1) + c0);
    const float4 b2v = *(const float4*)((const float*)(sm + OFF_B2) + c0);
    const float4 b3v = *(const float4*)((const float*)(sm + OFF_B3) + c0);

    for (int tile = blockIdx.x; tile < NTILES; tile += gridDim.x) {
        const int rbase = tile * TILE_M;

        // ---- gather -> X[k][r] (k-major); warp = 8 rows, lanes spread k ----
        {
            const int wrow = wid * 8;
            #pragma unroll 2
            for (int rr = 0; rr < 8; ++rr) {
                const int lr = wrow + rr;
                const size_t row = (size_t)(rbase + lr);
                sx[lane * XS + lr] = hist[row * HIST + lane];
                if (lane < HIST - 32)
                    sx[(32 + lane) * XS + lr] = hist[row * HIST + 32 + lane];
                sx[(HIST + lane) * XS + lr] = num[row * NUMD + lane];
                #pragma unroll
                for (int i = 0; i < 4; ++i) {
                    const int t = lane + 32 * i;
                    const int j = t >> 4, d = t & 15;
                    int idx = cat[row * NCAT + j];
                    idx = min(max(idx, 0), HASHB - 1);
                    sx[(HIST + NUMD + t) * XS + lr] = catT[(size_t)(j * HASHB + idx) * CATD + d];
                }
                int rid = region[row];
                rid = min(max(rid, 0), GEOB - 1);
                sx[(HIST + NUMD + NCAT * CATD + lane) * XS + lr] = regT[(size_t)rid * REGD + lane];
            }
        }
        __syncthreads();

        unsigned long long acc[4][2];

        // ---- layer 1 (K=242) ----
        gemm_rt<INDIM>(sx, sw1, r0, c0, acc);
        __syncthreads();                       // all X reads done (H aliases X)
        act_store(acc, b1v, sh, r0, c0);
        __syncthreads();                       // H ready

        // ---- layer 2 (K=64) ----
        gemm_rt<HID>(sh, sw2, r0, c0, acc);
        act_store(acc, b2v, sh2, r0, c0);      // H2 disjoint from H: no sync needed
        __syncthreads();                       // H2 ready

        // ---- layer 3 (K=64): dump logits (+bias) to scratch, row-major float4 ----
        gemm_rt<HID>(sh2, sw3, r0, c0, acc);
        {
            const float bb[4] = { b3v.x, b3v.y, b3v.z, b3v.w };
            #pragma unroll
            for (int r = 0; r < 4; ++r) {
                float l0, l1, l2, l3;
                upk2(acc[r][0], l0, l1);
                upk2(acc[r][1], l2, l3);
                *reinterpret_cast<float4*>(slg + (r0 + r) * LGS + c0) =
                    make_float4(l0 + bb[0], l1 + bb[1], l2 + bb[2], l3 + bb[3]);
            }
        }
        __syncthreads();

        // ---- overlapped epilogue ----
        // warps 4-15: zero the output tile directly in gmem (128 rows x 64 f32)
        // warps 0-3 : per-row top-8 + softmax (results held in registers)
        float sv[TOPK]; int si[TOPK];
        if (tid >= 128) {
            float4* obase = reinterpret_cast<float4*>(out + (size_t)rbase * KEXP);
            const float4 z = make_float4(0.f, 0.f, 0.f, 0.f);
            const int t = tid - 128;            // 0..383
            #pragma unroll
            for (int j = 0; j < 6; ++j) {
                const int idx = t + j * 384;    // 0..2047
                if (idx < 2048) obase[idx] = z;
            }
        } else {
            float v[KEXP];
            #pragma unroll
            for (int g = 0; g < 16; ++g) {
                const float4 t4 = *reinterpret_cast<const float4*>(slg + tid * LGS + g * 4);
                v[4 * g] = t4.x; v[4 * g + 1] = t4.y; v[4 * g + 2] = t4.z; v[4 * g + 3] = t4.w;
            }
            unsigned long long used = 0ull;
            #pragma unroll
            for (int it = 0; it < TOPK; ++it) {
                float bv = -INFINITY; int bi = 0;
                #pragma unroll
                for (int i = 0; i < KEXP; ++i) {
                    const bool take = (((used >> i) & 1ull) == 0ull) && (v[i] > bv);
                    if (take) { bv = v[i]; bi = i; }   // strict > : lowest index on ties
                }
                used |= 1ull << bi; sv[it] = bv; si[it] = bi;
            }
            const float vmax = sv[0];
            float ssum = 0.f;
            #pragma unroll
            for (int t = 0; t < TOPK; ++t) { sv[t] = expf(sv[t] - vmax); ssum += sv[t]; }
            const float inv = 1.0f / ssum;
            #pragma unroll
            for (int t = 0; t < TOPK; ++t) sv[t] *= inv;
        }
        __syncthreads();   // zeros globally ordered before scatters (same CTA)

        // warps 0-3: scatter the 8 alphas per row
        if (tid < 128) {
            float* orow = out + (size_t)(rbase + tid) * KEXP;
            #pragma unroll
            for (int t = 0; t < TOPK; ++t) orow[si[t]] = sv[t];
        }
        __syncthreads();   // slg (X region) free for next tile's gather
    }
}

extern "C" void kernel_launch(void* const* d_in, const int* in_sizes, int n_in,
                              void* d_out, int out_size)
{
    const float* hist   = (const float*)d_in[0];
    const float* num    = (const float*)d_in[1];
    const int*   cat    = (const int*)  d_in[2];
    const int*   region = (const int*)  d_in[3];
    const float* catT   = (const float*)d_in[4];
    const float* regT   = (const float*)d_in[5];
    const float* W1     = (const float*)d_in[6];
    const float* b1     = (const float*)d_in[7];
    const float* W2     = (const float*)d_in[8];
    const float* b2     = (const float*)d_in[9];
    const float* W3     = (const float*)d_in[10];
    const float* b3     = (const float*)d_in[11];
    float* out = (float*)d_out;

    cudaFuncSetAttribute(gating_kernel,
                         cudaFuncAttributeMaxDynamicSharedMemorySize, SMEM_TOTAL);
    gating_kernel<<<148, THREADS, SMEM_TOTAL>>>(
        hist, num, cat, region, catT, regT, W1, b1, W2, b2, W3, b3, out);
}